// round 16
// baseline (speedup 1.0000x reference)
#include <cuda_runtime.h>
#include <math.h>

// Problem constants
#define NB     32
#define NS     4096
#define ND     2048
#define DH     128
#define LUTN   4096
#define NSPLIT 16
#define SCHUNK (NS / NSPLIT)   // 256

// fp32 constants matching the reference computation
#define PHI_F   1.6180340f                 // (1+sqrt(5))/2 rounded to fp32
#define CONST_C 651.89865f                 // 4096 / (2*pi)
#define STEP_F  0.0015339808f              // (2*pi) / 4096
#define MAGIC_F 12582912.0f                // 1.5 * 2^23 (RN rounding shift)

// Device scratch (no allocations allowed in kernel_launch)
static __device__ float        g_scores[NB * NS];
// contiguous partials: g_partial[(sc*NB + b)*ND + d]  (coalesced writes)
static __device__ float        g_partial[NSPLIT * NB * ND];
// phase/ticket state, all zero-init and self-resetting -> graph-replay safe
static __device__ unsigned int g_aticket[NB];      // phase-A completion per batch
static __device__ unsigned int g_wdone[NB];        // softmax(b) published flag
static __device__ unsigned int g_dticket[NB * 4];  // out-partial reduce tickets
static __device__ unsigned int g_bticket[NB];      // phase-B completion per batch

// ---------------------------------------------------------------------------
// Quantized angle index (identical to reference LUT indexing)
// ---------------------------------------------------------------------------
__device__ __forceinline__ int qidx(float theta)
{
    return __float2int_rd(theta * CONST_C) & (LUTN - 1);
}

// cos(thq)cos(thk) + sin(thq)sin(thk) = cos((iq - ik) * STEP)
// cos is 2pi-periodic on the 4096-grid -> no masking of ik needed.
// floor via the magic-number RN trick: rn(f - 0.5) == floor(f) (the -0.5 is
// pre-folded into bkC2). Whole chain on the fma pipe; only cos touches MUFU.
__device__ __forceinline__ float dot_term(float v, float rkC, float bkC2,
                                          float angq)
{
    float f  = fmaf(v, rkC, bkC2);         // theta*C - 0.5
    float tm = f + MAGIC_F;                // RN -> MAGIC + floor(theta*C)
    float fr = tm - MAGIC_F;               // floor(theta*C) as float
    return __cosf(fmaf(fr, -STEP_F, angq));
}

// ---------------------------------------------------------------------------
// Fully fused kernel: per-batch pipeline of scores -> softmax -> output.
// grid: (64, NB) blocks of 128 threads. Block (b, j):
//   Phase A: scores for batch b, rows j*64 .. j*64+63 (4 warps x 16 rows)
//   last-arrival block per batch: softmax(b) -> weights in d_out, raise flag
//   Phase B: out-partial slice (dt = j&3, sc = j>>2) for batch b, gated on
//            the flag; last of 16 sc-blocks per (b,dt) reduces into out.
// Deadlock-free: phase A has no dependencies and runs before any spin; a
// batch's 64 blocks are bid-contiguous and wave-1 dispatch is bid-ordered.
// ---------------------------------------------------------------------------
__global__ void __launch_bounds__(128)
fused_kernel(const float* __restrict__ cs,
             const float* __restrict__ x,
             const float* __restrict__ t,
             const float* __restrict__ wq,
             const float* __restrict__ bq,
             const float* __restrict__ wk,
             const float* __restrict__ bk,
             float* __restrict__ out,      // (32, 2048)
             float* __restrict__ wout)     // (32, 4096)
{
    int j    = blockIdx.x;    // 0..63
    int b    = blockIdx.y;    // 0..31
    int tid  = threadIdx.x;   // 0..127
    int warp = tid >> 5;      // 0..3
    int lane = tid & 31;

    __shared__ float        red[8];
    __shared__ float        ws[SCHUNK];
    __shared__ unsigned int s_tick;

    // =============== Phase A: scores slice =================================
    {
        // lane owns d = 4*lane .. 4*lane+3
        float4 wk4 = *(const float4*)(wk + 4 * lane);
        float4 bk4 = *(const float4*)(bk + 4 * lane);
        float4 rkC = make_float4(CONST_C / (1.0f + fabsf(wk4.x)),
                                 CONST_C / (1.0f + fabsf(wk4.y)),
                                 CONST_C / (1.0f + fabsf(wk4.z)),
                                 CONST_C / (1.0f + fabsf(wk4.w)));
        float4 bkC2 = make_float4(fmaf(bk4.x, CONST_C, -0.5f),
                                  fmaf(bk4.y, CONST_C, -0.5f),
                                  fmaf(bk4.z, CONST_C, -0.5f),
                                  fmaf(bk4.w, CONST_C, -0.5f));

        float4 wq4 = *(const float4*)(wq + 4 * lane);
        float4 bq4 = *(const float4*)(bq + 4 * lane);
        float4 xq  = *(const float4*)(x + (size_t)b * ND + 4 * lane);
        float  tb  = t[b] * PHI_F;

        float aq0 = (float)qidx(fmaf(xq.x, 1.0f / (1.0f + fabsf(wq4.x)), bq4.x + tb)) * STEP_F;
        float aq1 = (float)qidx(fmaf(xq.y, 1.0f / (1.0f + fabsf(wq4.y)), bq4.y + tb)) * STEP_F;
        float aq2 = (float)qidx(fmaf(xq.z, 1.0f / (1.0f + fabsf(wq4.z)), bq4.z + tb)) * STEP_F;
        float aq3 = (float)qidx(fmaf(xq.w, 1.0f / (1.0f + fabsf(wq4.w)), bq4.w + tb)) * STEP_F;

        const float* base = cs + (size_t)b * NS * ND;
        int s0 = j * 64 + warp * 16;

        // 4 mini-batches of 4 rows: MLP=4 without register blowup.
        // Default caching: seeds L2 with the head patch for phase B.
        #pragma unroll
        for (int rr = 0; rr < 4; rr++) {
            float4 vv[4];
            #pragma unroll
            for (int r = 0; r < 4; r++)
                vv[r] = *(const float4*)(base
                        + (size_t)(s0 + rr * 4 + r) * ND + 4 * lane);
            #pragma unroll
            for (int r = 0; r < 4; r++) {
                float4 v = vv[r];
                float p0 = dot_term(v.x, rkC.x, bkC2.x, aq0);
                float p1 = dot_term(v.y, rkC.y, bkC2.y, aq1);
                float p2 = dot_term(v.z, rkC.z, bkC2.z, aq2);
                float p3 = dot_term(v.w, rkC.w, bkC2.w, aq3);
                float part = (p0 + p1) + (p2 + p3);
                #pragma unroll
                for (int o = 16; o > 0; o >>= 1)
                    part += __shfl_xor_sync(0xFFFFFFFFu, part, o);
                if (lane == 0)
                    g_scores[b * NS + s0 + rr * 4 + r] = part * 0.0625f;
            }
        }
    }

    // publish scores, count arrivals for this batch
    __threadfence();
    __syncthreads();
    if (tid == 0)
        s_tick = atomicAdd(&g_aticket[b], 1u);
    __syncthreads();

    // =============== Softmax(b) by the last-arriving block =================
    if (s_tick == 63u) {
        const float4* sc4 = (const float4*)(g_scores + b * NS);
        // pass 1: max
        float mx = -1e30f;
        #pragma unroll
        for (int k = 0; k < 8; k++) {
            float4 v = __ldcg(sc4 + tid + k * 128);
            mx = fmaxf(fmaxf(mx, fmaxf(v.x, v.y)), fmaxf(v.z, v.w));
        }
        #pragma unroll
        for (int o = 16; o > 0; o >>= 1)
            mx = fmaxf(mx, __shfl_xor_sync(0xFFFFFFFFu, mx, o));
        if (lane == 0) red[warp] = mx;
        __syncthreads();
        mx = fmaxf(fmaxf(red[0], red[1]), fmaxf(red[2], red[3]));
        // pass 2: sum of exp
        float sum = 0.0f;
        #pragma unroll
        for (int k = 0; k < 8; k++) {
            float4 v = __ldcg(sc4 + tid + k * 128);
            sum += __expf(v.x - mx) + __expf(v.y - mx)
                 + __expf(v.z - mx) + __expf(v.w - mx);
        }
        #pragma unroll
        for (int o = 16; o > 0; o >>= 1)
            sum += __shfl_xor_sync(0xFFFFFFFFu, sum, o);
        if (lane == 0) red[4 + warp] = sum;
        __syncthreads();
        float inv = 1.0f / (((red[4] + red[5]) + (red[6] + red[7])));
        // pass 3: write weights
        float4* w4 = (float4*)(wout + b * NS);
        #pragma unroll
        for (int k = 0; k < 8; k++) {
            float4 v = __ldcg(sc4 + tid + k * 128);
            float4 e = make_float4(__expf(v.x - mx) * inv,
                                   __expf(v.y - mx) * inv,
                                   __expf(v.z - mx) * inv,
                                   __expf(v.w - mx) * inv);
            w4[tid + k * 128] = e;
        }
        __threadfence();
        __syncthreads();
        if (tid == 0)
            atomicExch(&g_wdone[b], 1u);   // release
    }

    // =============== Phase B: output slice (gated on softmax flag) =========
    {
        int dt = j & 3;        // 0..3  (512-float d-tile)
        int sc = j >> 2;       // 0..15 (s-chunk)

        if (tid == 0) {
            while (((volatile unsigned int*)g_wdone)[b] == 0u)
                __nanosleep(64);
        }
        __syncthreads();       // acquire: orders subsequent loads after flag

        // stage this chunk's weights (L2-sourced, bypass L1)
        ws[tid]       = __ldcg(wout + b * NS + sc * SCHUNK + tid);
        ws[tid + 128] = __ldcg(wout + b * NS + sc * SCHUNK + tid + 128);
        __syncthreads();

        const float4* p = (const float4*)(cs
                          + ((size_t)(b * NS + sc * SCHUNK)) * ND
                          + dt * 512) + tid;
        float4 acc = make_float4(0.f, 0.f, 0.f, 0.f);
        #pragma unroll 8
        for (int s = 0; s < SCHUNK; s++) {
            float w  = ws[s];
            float4 v = __ldcs(p + (size_t)s * (ND / 4));
            acc.x = fmaf(w, v.x, acc.x);
            acc.y = fmaf(w, v.y, acc.y);
            acc.z = fmaf(w, v.z, acc.z);
            acc.w = fmaf(w, v.w, acc.w);
        }
        size_t off = (size_t)(sc * NB + b) * ND + dt * 512 + tid * 4;
        *(float4*)(g_partial + off) = acc;

        // last-block-done reduction for this (b, dt) slice
        __threadfence();
        __syncthreads();
        if (tid == 0)
            s_tick = atomicAdd(&g_dticket[b * 4 + dt], 1u);
        __syncthreads();
        if (s_tick == NSPLIT - 1) {
            size_t base2 = (size_t)b * ND + dt * 512 + tid * 4;
            float4 a = make_float4(0.f, 0.f, 0.f, 0.f);
            #pragma unroll
            for (int c = 0; c < NSPLIT; c++) {
                float4 v = __ldcg((const float4*)(g_partial
                                  + (size_t)c * NB * ND + base2));
                a.x += v.x; a.y += v.y; a.z += v.z; a.w += v.w;
            }
            *(float4*)(out + base2) = a;
            if (tid == 0)
                g_dticket[b * 4 + dt] = 0u;   // reset for next replay
        }
    }

    // =============== Per-batch state reset (graph-replay safe) =============
    __syncthreads();
    if (tid == 0) {
        unsigned int bt = atomicAdd(&g_bticket[b], 1u);
        if (bt == 63u) {       // all 64 blocks of batch b fully done
            g_aticket[b] = 0u;
            g_wdone[b]   = 0u;
            g_bticket[b] = 0u;
            __threadfence();
        }
    }
}

// ---------------------------------------------------------------------------
extern "C" void kernel_launch(void* const* d_in, const int* in_sizes, int n_in,
                              void* d_out, int out_size)
{
    const float* x  = (const float*)d_in[0];   // (32, 2048)
    const float* cs = (const float*)d_in[1];   // (32, 4096, 2048)
    const float* t  = (const float*)d_in[2];   // (32,)
    const float* wq = (const float*)d_in[3];   // (128,)
    const float* bq = (const float*)d_in[4];   // (128,)
    const float* wk = (const float*)d_in[5];   // (128,)
    const float* bk = (const float*)d_in[6];   // (128,)

    float* out_main = (float*)d_out;            // (32, 2048)
    float* out_wts  = out_main + NB * ND;       // (32, 4096)

    dim3 g(64, NB);
    fused_kernel<<<g, 128>>>(cs, x, t, wq, bq, wk, bk, out_main, out_wts);
}

// round 17
// speedup vs baseline: 1.1280x; 1.1280x over previous
#include <cuda_runtime.h>
#include <math.h>

// Problem constants
#define NB     32
#define NS     4096
#define ND     2048
#define DH     128
#define LUTN   4096
#define NSPLIT 16
#define SCHUNK (NS / NSPLIT)   // 256

// fp32 constants matching the reference computation
#define PHI_F   1.6180340f                 // (1+sqrt(5))/2 rounded to fp32
#define CONST_C 651.89865f                 // 4096 / (2*pi)
#define STEP_F  0.0015339808f              // (2*pi) / 4096
#define MAGIC_F 12582912.0f                // 1.5 * 2^23 (RN rounding shift)

// Device scratch (no allocations allowed in kernel_launch)
static __device__ float        g_scores[NB * NS];
// contiguous partials: g_partial[(sc*NB + b)*ND + d]  (coalesced writes)
static __device__ float        g_partial[NSPLIT * NB * ND];
// tickets (zero-init, self-resetting -> graph-replay safe)
static __device__ unsigned int g_aticket[NB];      // scores completion per batch
static __device__ unsigned int g_dticket[NB * 4];  // out-partial reduce tickets

// ---------------------------------------------------------------------------
// Quantized angle index (identical to reference LUT indexing)
// ---------------------------------------------------------------------------
__device__ __forceinline__ int qidx(float theta)
{
    return __float2int_rd(theta * CONST_C) & (LUTN - 1);
}

// cos(thq)cos(thk) + sin(thq)sin(thk) = cos((iq - ik) * STEP)
// cos is 2pi-periodic on the 4096-grid -> no masking of ik needed.
// floor via the magic-number RN trick: rn(f - 0.5) == floor(f) (the -0.5 is
// pre-folded into bkC2). Whole chain on the fma pipe; only cos touches MUFU.
__device__ __forceinline__ float dot_term(float v, float rkC, float bkC2,
                                          float angq)
{
    float f  = fmaf(v, rkC, bkC2);         // theta*C - 0.5
    float tm = f + MAGIC_F;                // RN -> MAGIC + floor(theta*C)
    float fr = tm - MAGIC_F;               // floor(theta*C) as float
    return __cosf(fmaf(fr, -STEP_F, angq));
}

// ---------------------------------------------------------------------------
// Kernel B: scores[b,s] = (1/16) * sum_d cos(theta_q - theta_k) [quantized]
// + ticket-gated softmax(b) by the last-arriving block of each batch
//   (scores are L2-hot at that point; saves a kernel launch).
// Loads use DEFAULT caching so the 64 MB head-patch stays in L2 for
// out_partial to re-hit.
// grid: (NS/64, NB), block 256 (8 warps, each warp does 8 rows)
// ---------------------------------------------------------------------------
__global__ void scores_kernel(const float* __restrict__ cs,
                              const float* __restrict__ x,
                              const float* __restrict__ t,
                              const float* __restrict__ wq,
                              const float* __restrict__ bq,
                              const float* __restrict__ wk,
                              const float* __restrict__ bk,
                              float* __restrict__ wout)
{
    int tid  = threadIdx.x;
    int b    = blockIdx.y;
    int warp = tid >> 5;
    int lane = tid & 31;

    __shared__ float        red[16];
    __shared__ unsigned int s_tick;

    // lane owns d = 4*lane .. 4*lane+3 : precompute scaled key params and
    // quantized query angles locally
    float4 wk4 = *(const float4*)(wk + 4 * lane);
    float4 bk4 = *(const float4*)(bk + 4 * lane);
    float4 rkC = make_float4(CONST_C / (1.0f + fabsf(wk4.x)),
                             CONST_C / (1.0f + fabsf(wk4.y)),
                             CONST_C / (1.0f + fabsf(wk4.z)),
                             CONST_C / (1.0f + fabsf(wk4.w)));
    // bk*C with the floor-trick's -0.5 pre-folded in
    float4 bkC2 = make_float4(fmaf(bk4.x, CONST_C, -0.5f),
                              fmaf(bk4.y, CONST_C, -0.5f),
                              fmaf(bk4.z, CONST_C, -0.5f),
                              fmaf(bk4.w, CONST_C, -0.5f));

    float4 wq4 = *(const float4*)(wq + 4 * lane);
    float4 bq4 = *(const float4*)(bq + 4 * lane);
    float4 xq  = *(const float4*)(x + (size_t)b * ND + 4 * lane);
    float  tb  = t[b] * PHI_F;

    // masked query indices (matches reference exactly), as grid angles
    float aq0 = (float)qidx(fmaf(xq.x, 1.0f / (1.0f + fabsf(wq4.x)), bq4.x + tb)) * STEP_F;
    float aq1 = (float)qidx(fmaf(xq.y, 1.0f / (1.0f + fabsf(wq4.y)), bq4.y + tb)) * STEP_F;
    float aq2 = (float)qidx(fmaf(xq.z, 1.0f / (1.0f + fabsf(wq4.z)), bq4.z + tb)) * STEP_F;
    float aq3 = (float)qidx(fmaf(xq.w, 1.0f / (1.0f + fabsf(wq4.w)), bq4.w + tb)) * STEP_F;

    const float* base = cs + (size_t)b * NS * ND;
    int s0 = blockIdx.x * 64 + warp * 8;

    #pragma unroll
    for (int r = 0; r < 8; r++) {
        int s = s0 + r;
        // default caching: seed L2 with the head patch for out_partial
        float4 v = *(const float4*)(base + (size_t)s * ND + 4 * lane);
        float p0 = dot_term(v.x, rkC.x, bkC2.x, aq0);
        float p1 = dot_term(v.y, rkC.y, bkC2.y, aq1);
        float p2 = dot_term(v.z, rkC.z, bkC2.z, aq2);
        float p3 = dot_term(v.w, rkC.w, bkC2.w, aq3);
        float part = (p0 + p1) + (p2 + p3);
        #pragma unroll
        for (int o = 16; o > 0; o >>= 1)
            part += __shfl_xor_sync(0xFFFFFFFFu, part, o);
        if (lane == 0)
            g_scores[b * NS + s] = part * 0.0625f;  // / sqrt(2*128) = /16
    }

    // ---- ticket: last-arriving block of this batch runs softmax(b) ----
    __threadfence();      // publish this block's scores
    __syncthreads();      // all warps stored + fenced
    if (tid == 0)
        s_tick = atomicAdd(&g_aticket[b], 1u);
    __syncthreads();
    if (s_tick != 63u)
        return;

    // ---- softmax over g_scores[b, :] (256 threads, 16 elems each) ----
    const float4* sc4 = (const float4*)(g_scores + b * NS);   // 1024 float4
    float4 vv[4];
    float mx = -1e30f;
    #pragma unroll
    for (int k = 0; k < 4; k++) {
        vv[k] = __ldcg(sc4 + tid + k * 256);
        mx = fmaxf(fmaxf(mx, fmaxf(vv[k].x, vv[k].y)),
                   fmaxf(vv[k].z, vv[k].w));
    }
    #pragma unroll
    for (int o = 16; o > 0; o >>= 1)
        mx = fmaxf(mx, __shfl_xor_sync(0xFFFFFFFFu, mx, o));
    if (lane == 0) red[warp] = mx;
    __syncthreads();
    mx = fmaxf(fmaxf(fmaxf(red[0], red[1]), fmaxf(red[2], red[3])),
               fmaxf(fmaxf(red[4], red[5]), fmaxf(red[6], red[7])));

    float sum = 0.0f;
    #pragma unroll
    for (int k = 0; k < 4; k++) {
        vv[k].x = __expf(vv[k].x - mx);
        vv[k].y = __expf(vv[k].y - mx);
        vv[k].z = __expf(vv[k].z - mx);
        vv[k].w = __expf(vv[k].w - mx);
        sum += (vv[k].x + vv[k].y) + (vv[k].z + vv[k].w);
    }
    #pragma unroll
    for (int o = 16; o > 0; o >>= 1)
        sum += __shfl_xor_sync(0xFFFFFFFFu, sum, o);
    if (lane == 0) red[8 + warp] = sum;
    __syncthreads();
    float inv = 1.0f / (((red[8]  + red[9])  + (red[10] + red[11]))
                      + ((red[12] + red[13]) + (red[14] + red[15])));

    float4* w4 = (float4*)(wout + b * NS);
    #pragma unroll
    for (int k = 0; k < 4; k++) {
        float4 e = make_float4(vv[k].x * inv, vv[k].y * inv,
                               vv[k].z * inv, vv[k].w * inv);
        w4[tid + k * 256] = e;
    }
    if (tid == 0)
        g_aticket[b] = 0u;    // reset for next graph replay
}

// ---------------------------------------------------------------------------
// Kernel D: partial[sc][b][d] = sum_{s in chunk} w[b,s] * cs[b,s,d]
// plus fused last-block-done reduction into out (no separate reduce launch).
// grid: (4 d-tiles, NSPLIT s-chunks, NB batches), block 128 (thread = float4)
// __ldcs on cs: evict-first streaming preserves the scores-seeded head-patch
// lines in L2 (dt=0 re-hits). Partial writes are contiguous/coalesced.
// Release order: store -> __threadfence -> __syncthreads -> tid0 atomicAdd
// (canonical threadFenceReduction pattern).
// ---------------------------------------------------------------------------
__global__ void out_partial_kernel(const float* __restrict__ cs,
                                   const float* __restrict__ wts,
                                   float* __restrict__ out)
{
    int dt  = blockIdx.x;     // 0..3, 512 floats each
    int sc  = blockIdx.y;     // 0..NSPLIT-1
    int b   = blockIdx.z;
    int tid = threadIdx.x;    // 0..127

    __shared__ float ws[SCHUNK];
    __shared__ unsigned int s_ticket;
    #pragma unroll
    for (int k = 0; k < SCHUNK / 128; k++)
        ws[tid + k * 128] = wts[b * NS + sc * SCHUNK + tid + k * 128];
    __syncthreads();

    const float4* p = (const float4*)(cs + ((size_t)(b * NS + sc * SCHUNK)) * ND
                                         + dt * 512) + tid;
    float4 acc = make_float4(0.f, 0.f, 0.f, 0.f);
    #pragma unroll 8
    for (int s = 0; s < SCHUNK; s++) {
        float w  = ws[s];
        float4 v = __ldcs(p + (size_t)s * (ND / 4));
        acc.x = fmaf(w, v.x, acc.x);
        acc.y = fmaf(w, v.y, acc.y);
        acc.z = fmaf(w, v.z, acc.z);
        acc.w = fmaf(w, v.w, acc.w);
    }
    size_t off = (size_t)(sc * NB + b) * ND + dt * 512 + tid * 4;
    *(float4*)(g_partial + off) = acc;

    // ---- last-block-done reduction for this (b, dt) slice ----
    __threadfence();      // make THIS thread's partial store globally visible
    __syncthreads();      // ensure ALL 128 threads have stored + fenced
    if (tid == 0)
        s_ticket = atomicAdd(&g_dticket[b * 4 + dt], 1u);
    __syncthreads();
    if (s_ticket == NSPLIT - 1) {
        // all 16 partials for (b, dt) are globally visible; reduce in fixed
        // c-order (deterministic). __ldcg bypasses L1 (no stale-copy risk).
        size_t base = (size_t)b * ND + dt * 512 + tid * 4;
        float4 a = make_float4(0.f, 0.f, 0.f, 0.f);
        #pragma unroll
        for (int c = 0; c < NSPLIT; c++) {
            float4 v = __ldcg((const float4*)(g_partial
                              + (size_t)c * NB * ND + base));
            a.x += v.x; a.y += v.y; a.z += v.z; a.w += v.w;
        }
        *(float4*)(out + base) = a;
        if (tid == 0)
            g_dticket[b * 4 + dt] = 0u;     // reset for next graph replay
    }
}

// ---------------------------------------------------------------------------
extern "C" void kernel_launch(void* const* d_in, const int* in_sizes, int n_in,
                              void* d_out, int out_size)
{
    const float* x  = (const float*)d_in[0];   // (32, 2048)
    const float* cs = (const float*)d_in[1];   // (32, 4096, 2048)
    const float* t  = (const float*)d_in[2];   // (32,)
    const float* wq = (const float*)d_in[3];   // (128,)
    const float* bq = (const float*)d_in[4];   // (128,)
    const float* wk = (const float*)d_in[5];   // (128,)
    const float* bk = (const float*)d_in[6];   // (128,)

    float* out_main = (float*)d_out;            // (32, 2048)
    float* out_wts  = out_main + NB * ND;       // (32, 4096)

    dim3 gS(NS / 64, NB);
    scores_kernel<<<gS, 256>>>(cs, x, t, wq, bq, wk, bk, out_wts);

    dim3 gO(4, NSPLIT, NB);
    out_partial_kernel<<<gO, 128>>>(cs, out_wts, out_main);
}